// round 10
// baseline (speedup 1.0000x reference)
#include <cuda_runtime.h>
#include <cuda_fp16.h>
#include <cstdint>

// FP4(E2M1) weight-only linear, fused persistent kernel with cp.async pipeline:
//   phase 0: build fp16 activation fragments (amax folded)
//   phase 1: fp16 mma.sync GEMM; qweight/scales/bfrag staged through a 4-deep
//            cp.async SMEM pipeline (loads decoupled from register scoreboard)
//   phase 2: split-K reduce + bias
// out[32,8192] = inp[32,8192] @ W^T + bias, W[n,k]=LUT(nib)*scales[n,k/16]*amax

#define TOKENS   32
#define NFEAT    8192
#define KFEAT    8192
#define NWIN     (KFEAT / 16)
#define NMP      (NWIN / 2)            // 256 window-pairs
#define KSPLIT   8
#define MP_PER_CTA  (NMP / KSPLIT)     // 32
#define NCTAS    512

#define NSTAGES     4
#define QS_BYTES    8192               // 128 rows x 64 B (32 k of packed nibbles)
#define BFS_BYTES   2048               // 128 x uint4 activation fragments
#define SS_BYTES    1024               // 128 x float2 scales
#define STAGE_BYTES (QS_BYTES + BFS_BYTES + SS_BYTES)   // 11264; x4 = 45056 B

__device__ uint4 g_bfrag[NMP * 4 * 32];             // fp16x2 x4 per [mp][g][lane] (2 MB)
__device__ float g_part[KSPLIT * TOKENS * NFEAT];   // split-K partials (8 MB)
__device__ unsigned g_cnt[2];                        // barrier counters (zero-init)
__device__ volatile unsigned g_phase[2];             // barrier phase flags

// ---------- helpers ----------
__device__ __forceinline__ uint32_t smem_u32(const void* p){
    uint32_t a;
    asm("{ .reg .u64 t; cvta.to.shared.u64 t, %1; cvt.u32.u64 %0, t; }" : "=r"(a) : "l"(p));
    return a;
}
#define CPA16(dst, src) asm volatile("cp.async.cg.shared.global [%0], [%1], 16;" :: "r"(dst), "l"(src))
#define CPA8(dst, src)  asm volatile("cp.async.ca.shared.global [%0], [%1], 8;"  :: "r"(dst), "l"(src))
#define CPA_COMMIT()    asm volatile("cp.async.commit_group;")
#define CPA_WAIT2()     asm volatile("cp.async.wait_group 2;")

__device__ __forceinline__ uint32_t dec16(uint32_t b){   // byte -> fp16x2 LUT pair (exact)
    uint32_t h = __byte_perm(0x3E3C3800u, 0x46444240u, b & 0x77u);
    uint32_t r = __byte_perm(h, 0u, 0x1404u);
    return r | ((b & 0x8u) << 12) | ((b & 0x80u) << 24);
}
__device__ __forceinline__ uint32_t hmul2(uint32_t a, uint32_t b){
    uint32_t r; asm("mul.rn.f16x2 %0, %1, %2;" : "=r"(r) : "r"(a), "r"(b)); return r;
}
__device__ __forceinline__ uint32_t dup_f16(float s){
    uint32_t r; asm("cvt.rn.f16x2.f32 %0, %1, %1;" : "=r"(r) : "f"(s)); return r;
}
__device__ __forceinline__ uint32_t pack_f16x2(float lo, float hi){
    uint32_t r; asm("cvt.rn.f16x2.f32 %0, %1, %2;" : "=r"(r) : "f"(hi), "f"(lo)); return r;
}
__device__ __forceinline__ void mma_acc(
    float& d0, float& d1, float& d2, float& d3,
    uint32_t a0, uint32_t a1, uint32_t a2, uint32_t a3,
    uint32_t b0, uint32_t b1)
{
    asm("mma.sync.aligned.m16n8k16.row.col.f32.f16.f16.f32 "
        "{%0,%1,%2,%3}, {%4,%5,%6,%7}, {%8,%9}, {%0,%1,%2,%3};"
        : "+f"(d0), "+f"(d1), "+f"(d2), "+f"(d3)
        : "r"(a0), "r"(a1), "r"(a2), "r"(a3), "r"(b0), "r"(b1));
}

// sense-reversing grid barrier; replay-safe (counter self-resets, phase toggles)
__device__ __forceinline__ void grid_barrier(int b){
    __syncthreads();
    if (threadIdx.x == 0){
        __threadfence();
        unsigned p = g_phase[b];
        unsigned arrived = atomicAdd(&g_cnt[b], 1u) + 1u;
        if (arrived == NCTAS){
            g_cnt[b] = 0u;
            __threadfence();
            g_phase[b] = p + 1u;
        } else {
            while (g_phase[b] == p) { __nanosleep(32); }
        }
    }
    __syncthreads();
    __threadfence();
}

// ---------------- fused persistent kernel ----------------
// grid (64, 8) = 512 CTAs, 128 thr; SMEM 44 KB/CTA -> occ 4 (1 wave).
__global__ void __launch_bounds__(128, 4) fp4_fused_kernel(
    const int*   __restrict__ qw,       // [N, K/2] one packed byte per int32
    const float* __restrict__ scales,   // [N, K/16]
    const float* __restrict__ inp,      // [M, K]
    const float* __restrict__ amax,     // [1]
    const float* __restrict__ bias,     // [N]
    float*       __restrict__ out)      // [M, N]
{
    __shared__ __align__(16) char smem[NSTAGES * STAGE_BYTES];

    const int tid = threadIdx.x, wid = tid >> 5, lane = tid & 31;
    const int c  = lane & 3, rl = lane >> 2;
    const int bid = blockIdx.y * 64 + blockIdx.x;
    const int t   = bid * 128 + tid;                  // flat 0..65535

    // ========== phase 0: build fp16 B fragments (one uint2 per thread) ==========
    {
        int e = t >> 1, h = t & 1;
        int bl = e & 31, g = (e >> 5) & 3, mp = e >> 7;
        int bc = bl & 3, n = g * 8 + (bl >> 2);
        int k0 = 32 * mp + 8 * bc + 4 * h;
        const float am = __ldg(amax);
        float4 a = *reinterpret_cast<const float4*>(inp + (size_t)n * KFEAT + k0);
        reinterpret_cast<uint2*>(g_bfrag)[t] =
            make_uint2(pack_f16x2(a.x * am, a.y * am), pack_f16x2(a.z * am, a.w * am));
    }
    grid_barrier(0);

    // ========== phase 1: GEMM with cp.async 4-stage pipeline ==========
    {
        const int nb0 = blockIdx.x * 128;
        const int r0  = nb0 + wid * 32 + rl;              // rows r0,+8,+16,+24
        const int mpb = blockIdx.y * MP_PER_CTA;
        const bool hiblk = (lane & 2) != 0;
        const uint32_t sbase = smem_u32(smem);

        // advancing cp.async source pointers (one mp step = +64 / +2048 / +8 bytes)
        const char* qsrc = (const char*)qw
            + ((size_t)(nb0 + wid * 32 + rl) * (KFEAT / 2) + (size_t)mpb * 16 + c * 4) * 4;
        const char* bsrc = (const char*)g_bfrag + ((size_t)mpb * 128 + tid) * 16;
        const char* ssrc = (const char*)scales + ((size_t)(nb0 + tid) * NWIN + (size_t)mpb * 2) * 4;

        // per-thread SMEM destinations within a stage
        const uint32_t qdst_base = sbase + (uint32_t)((wid * 32 + rl) * 64 + c * 16);
        const uint32_t bdst_base = sbase + QS_BYTES + (uint32_t)tid * 16;
        const uint32_t sdst_base = sbase + QS_BYTES + BFS_BYTES + (uint32_t)tid * 8;

        float acc[4][8];
        #pragma unroll
        for (int g = 0; g < 4; ++g)
            #pragma unroll
            for (int j = 0; j < 8; ++j) acc[g][j] = 0.f;

        // ---- pipeline prologue: issue stages 0..2 ----
        #pragma unroll
        for (int s = 0; s < NSTAGES - 1; ++s){
            const uint32_t so = (uint32_t)s * STAGE_BYTES;
            #pragma unroll
            for (int i = 0; i < 4; ++i)
                CPA16(qdst_base + so + i * 8 * 64, qsrc + (size_t)i * 8 * (KFEAT / 2) * 4);
            CPA16(bdst_base + so, bsrc);
            CPA8 (sdst_base + so, ssrc);
            CPA_COMMIT();
            qsrc += 64; bsrc += 2048; ssrc += 8;
        }

        #pragma unroll 1
        for (int mpl = 0; mpl < MP_PER_CTA; ++mpl){
            CPA_WAIT2();
            __syncthreads();

            // issue stage mpl+3 (into the buffer consumed at mpl-1)
            if (mpl + NSTAGES - 1 < MP_PER_CTA){
                const uint32_t so = (uint32_t)((mpl + NSTAGES - 1) & (NSTAGES - 1)) * STAGE_BYTES;
                #pragma unroll
                for (int i = 0; i < 4; ++i)
                    CPA16(qdst_base + so + i * 8 * 64, qsrc + (size_t)i * 8 * (KFEAT / 2) * 4);
                CPA16(bdst_base + so, bsrc);
                CPA8 (sdst_base + so, ssrc);
                qsrc += 64; bsrc += 2048; ssrc += 8;
            }
            CPA_COMMIT();

            // ---- compute from stage mpl%4 ----
            const char* cb = smem + (mpl & (NSTAGES - 1)) * STAGE_BYTES;

            const uint4 q0 = *reinterpret_cast<const uint4*>(cb + (wid * 32 +  0 + rl) * 64 + c * 16);
            const uint4 q1 = *reinterpret_cast<const uint4*>(cb + (wid * 32 +  8 + rl) * 64 + c * 16);
            const uint4 q2 = *reinterpret_cast<const uint4*>(cb + (wid * 32 + 16 + rl) * 64 + c * 16);
            const uint4 q3 = *reinterpret_cast<const uint4*>(cb + (wid * 32 + 24 + rl) * 64 + c * 16);

            const float2 t0 = *reinterpret_cast<const float2*>(cb + QS_BYTES + BFS_BYTES + (wid * 32 +  0 + rl) * 8);
            const float2 t1 = *reinterpret_cast<const float2*>(cb + QS_BYTES + BFS_BYTES + (wid * 32 +  8 + rl) * 8);
            const float2 t2 = *reinterpret_cast<const float2*>(cb + QS_BYTES + BFS_BYTES + (wid * 32 + 16 + rl) * 8);
            const float2 t3 = *reinterpret_cast<const float2*>(cb + QS_BYTES + BFS_BYTES + (wid * 32 + 24 + rl) * 8);
            const uint32_t h0 = dup_f16(hiblk ? t0.y : t0.x);
            const uint32_t h1 = dup_f16(hiblk ? t1.y : t1.x);
            const uint32_t h2 = dup_f16(hiblk ? t2.y : t2.x);
            const uint32_t h3 = dup_f16(hiblk ? t3.y : t3.x);

            uint4 bf[4];
            #pragma unroll
            for (int g = 0; g < 4; ++g)
                bf[g] = *reinterpret_cast<const uint4*>(cb + QS_BYTES + (g * 32 + lane) * 16);

            {   // e = 0 (k 0..15 of pair)
                const uint32_t a00 = hmul2(dec16(q0.x), h0), a02 = hmul2(dec16(q0.y), h0);
                const uint32_t a01 = hmul2(dec16(q1.x), h1), a03 = hmul2(dec16(q1.y), h1);
                const uint32_t a10 = hmul2(dec16(q2.x), h2), a12 = hmul2(dec16(q2.y), h2);
                const uint32_t a11 = hmul2(dec16(q3.x), h3), a13 = hmul2(dec16(q3.y), h3);
                #pragma unroll
                for (int g = 0; g < 4; ++g){
                    mma_acc(acc[g][0], acc[g][1], acc[g][2], acc[g][3],
                            a00, a01, a02, a03, bf[g].x, bf[g].y);
                    mma_acc(acc[g][4], acc[g][5], acc[g][6], acc[g][7],
                            a10, a11, a12, a13, bf[g].x, bf[g].y);
                }
            }
            {   // e = 1 (k 16..31 of pair)
                const uint32_t a00 = hmul2(dec16(q0.z), h0), a02 = hmul2(dec16(q0.w), h0);
                const uint32_t a01 = hmul2(dec16(q1.z), h1), a03 = hmul2(dec16(q1.w), h1);
                const uint32_t a10 = hmul2(dec16(q2.z), h2), a12 = hmul2(dec16(q2.w), h2);
                const uint32_t a11 = hmul2(dec16(q3.z), h3), a13 = hmul2(dec16(q3.w), h3);
                #pragma unroll
                for (int g = 0; g < 4; ++g){
                    mma_acc(acc[g][0], acc[g][1], acc[g][2], acc[g][3],
                            a00, a01, a02, a03, bf[g].z, bf[g].w);
                    mma_acc(acc[g][4], acc[g][5], acc[g][6], acc[g][7],
                            a10, a11, a12, a13, bf[g].z, bf[g].w);
                }
            }
        }

        // write split-K partials: token cols g*8+2c, 2c+1 ; rows r0, +8, +16, +24
        float* base = g_part + (size_t)blockIdx.y * (TOKENS * NFEAT);
        #pragma unroll
        for (int g = 0; g < 4; ++g){
            const int t0c = g * 8 + 2 * c;
            base[(size_t)t0c       * NFEAT + r0     ] = acc[g][0];
            base[(size_t)(t0c + 1) * NFEAT + r0     ] = acc[g][1];
            base[(size_t)t0c       * NFEAT + r0 +  8] = acc[g][2];
            base[(size_t)(t0c + 1) * NFEAT + r0 +  8] = acc[g][3];
            base[(size_t)t0c       * NFEAT + r0 + 16] = acc[g][4];
            base[(size_t)(t0c + 1) * NFEAT + r0 + 16] = acc[g][5];
            base[(size_t)t0c       * NFEAT + r0 + 24] = acc[g][6];
            base[(size_t)(t0c + 1) * NFEAT + r0 + 24] = acc[g][7];
        }
    }
    grid_barrier(1);

    // ========== phase 2: split-K reduce + bias (one float4 per thread) ==========
    {
        const int i4 = t;
        const float4 b = *reinterpret_cast<const float4*>(bias + ((i4 * 4) & (NFEAT - 1)));
        float4 s = b;
        #pragma unroll
        for (int cp = 0; cp < KSPLIT; ++cp){
            const float4 v = *reinterpret_cast<const float4*>(
                g_part + (size_t)cp * (TOKENS * NFEAT) + (size_t)i4 * 4);
            s.x += v.x; s.y += v.y; s.z += v.z; s.w += v.w;
        }
        reinterpret_cast<float4*>(out)[i4] = s;
    }
}

extern "C" void kernel_launch(void* const* d_in, const int* in_sizes, int n_in,
                              void* d_out, int out_size)
{
    const float* inp    = (const float*)d_in[0];
    const int*   qw     = (const int*)  d_in[1];
    const float* scales = (const float*)d_in[2];
    const float* amax   = (const float*)d_in[3];
    const float* bias   = (const float*)d_in[4];
    float* out = (float*)d_out;

    dim3 grid(NFEAT / 128, KSPLIT);
    fp4_fused_kernel<<<grid, 128>>>(qw, scales, inp, amax, bias, out);
}

// round 11
// speedup vs baseline: 1.2259x; 1.2259x over previous
#include <cuda_runtime.h>
#include <cuda_fp16.h>
#include <cstdint>

// FP4(E2M1) weight-only linear, fused persistent kernel, occupancy-8 GEMM:
//   phase 0: build fp16 activation fragments (amax folded)
//   phase 1: fp16 mma.sync GEMM, 16 rows/warp, scales folded into fp16 A regs
//   phase 2: split-K reduce + bias
// out[32,8192] = inp[32,8192] @ W^T + bias, W[n,k]=LUT(nib)*scales[n,k/16]*amax

#define TOKENS   32
#define NFEAT    8192
#define KFEAT    8192
#define NWIN     (KFEAT / 16)          // 512 mma k-steps
#define NMP      (NWIN / 2)            // 256 window-pairs
#define KSPLIT   8
#define MP_PER_CTA  (NMP / KSPLIT)     // 32
#define NCTAS    1024

__device__ uint4 g_bfrag[NMP * 4 * 32];             // fp16x2 x4 per [mp][g][lane] (2 MB)
__device__ float g_part[KSPLIT * TOKENS * NFEAT];   // split-K partials (8 MB)
__device__ unsigned g_cnt[2];                        // barrier counters (zero-init)
__device__ volatile unsigned g_phase[2];             // barrier phase flags

// ---------- helpers ----------
__device__ __forceinline__ uint32_t dec16(uint32_t b){   // byte -> fp16x2 LUT pair (exact)
    uint32_t h = __byte_perm(0x3E3C3800u, 0x46444240u, b & 0x77u);
    uint32_t r = __byte_perm(h, 0u, 0x1404u);
    return r | ((b & 0x8u) << 12) | ((b & 0x80u) << 24);
}
__device__ __forceinline__ uint32_t hmul2(uint32_t a, uint32_t b){
    uint32_t r; asm("mul.rn.f16x2 %0, %1, %2;" : "=r"(r) : "r"(a), "r"(b)); return r;
}
__device__ __forceinline__ uint32_t dup_f16(float s){
    uint32_t r; asm("cvt.rn.f16x2.f32 %0, %1, %1;" : "=r"(r) : "f"(s)); return r;
}
__device__ __forceinline__ uint32_t pack_f16x2(float lo, float hi){
    uint32_t r; asm("cvt.rn.f16x2.f32 %0, %1, %2;" : "=r"(r) : "f"(hi), "f"(lo)); return r;
}
__device__ __forceinline__ void mma_acc(
    float& d0, float& d1, float& d2, float& d3,
    uint32_t a0, uint32_t a1, uint32_t a2, uint32_t a3,
    uint32_t b0, uint32_t b1)
{
    asm("mma.sync.aligned.m16n8k16.row.col.f32.f16.f16.f32 "
        "{%0,%1,%2,%3}, {%4,%5,%6,%7}, {%8,%9}, {%0,%1,%2,%3};"
        : "+f"(d0), "+f"(d1), "+f"(d2), "+f"(d3)
        : "r"(a0), "r"(a1), "r"(a2), "r"(a3), "r"(b0), "r"(b1));
}

// sense-reversing grid barrier; replay-safe (counter self-resets, phase toggles)
__device__ __forceinline__ void grid_barrier(int b){
    __syncthreads();
    if (threadIdx.x == 0){
        __threadfence();
        unsigned p = g_phase[b];
        unsigned arrived = atomicAdd(&g_cnt[b], 1u) + 1u;
        if (arrived == NCTAS){
            g_cnt[b] = 0u;
            __threadfence();
            g_phase[b] = p + 1u;
        } else {
            while (g_phase[b] == p) { __nanosleep(32); }
        }
    }
    __syncthreads();
    __threadfence();
}

// ---------------- fused persistent kernel ----------------
// grid (128, 8) = 1024 CTAs, 128 thr, occ 8 (reg cap 64) -> all co-resident.
__global__ void __launch_bounds__(128, 8) fp4_fused_kernel(
    const int*   __restrict__ qw,       // [N, K/2] one packed byte per int32
    const float* __restrict__ scales,   // [N, K/16]
    const float* __restrict__ inp,      // [M, K]
    const float* __restrict__ amax,     // [1]
    const float* __restrict__ bias,     // [N]
    float*       __restrict__ out)      // [M, N]
{
    const int tid = threadIdx.x, wid = tid >> 5, lane = tid & 31;
    const int bid = blockIdx.y * 128 + blockIdx.x;
    const int t   = bid * 128 + tid;                  // flat 0..131071

    // ========== phase 0: build fp16 B fragments (first 65536 threads) ==========
    if (t < NMP * 4 * 32 * 2){
        int e = t >> 1, h = t & 1;
        int bl = e & 31, g = (e >> 5) & 3, mp = e >> 7;
        int bc = bl & 3, n = g * 8 + (bl >> 2);
        int k0 = 32 * mp + 8 * bc + 4 * h;
        const float am = __ldg(amax);
        float4 a = *reinterpret_cast<const float4*>(inp + (size_t)n * KFEAT + k0);
        reinterpret_cast<uint2*>(g_bfrag)[t] =
            make_uint2(pack_f16x2(a.x * am, a.y * am), pack_f16x2(a.z * am, a.w * am));
    }
    grid_barrier(0);

    // ========== phase 1: GEMM, 16 rows/warp ==========
    {
        const int c  = lane & 3;
        const int r0 = blockIdx.x * 64 + wid * 16 + (lane >> 2);   // rows r0, r0+8
        const int mpb = blockIdx.y * MP_PER_CTA;
        const bool hiblk = (lane & 2) != 0;

        float acc[4][4];
        #pragma unroll
        for (int g = 0; g < 4; ++g)
            #pragma unroll
            for (int j = 0; j < 4; ++j) acc[g][j] = 0.f;

        const uint4* qr0 = reinterpret_cast<const uint4*>(qw + (size_t)(r0    ) * (KFEAT / 2)) + c;
        const uint4* qr1 = reinterpret_cast<const uint4*>(qw + (size_t)(r0 + 8) * (KFEAT / 2)) + c;
        const float2* sr0 = reinterpret_cast<const float2*>(scales + (size_t)(r0    ) * NWIN);
        const float2* sr1 = reinterpret_cast<const float2*>(scales + (size_t)(r0 + 8) * NWIN);

        #pragma unroll 4
        for (int mpl = 0; mpl < MP_PER_CTA; ++mpl){
            const int mp = mpb + mpl;

            const uint4 q0 = __ldg(qr0 + mp * 4);       // row r0,   32 k
            const uint4 q1 = __ldg(qr1 + mp * 4);       // row r0+8, 32 k

            const float2 t0 = __ldg(sr0 + mp);
            const float2 t1 = __ldg(sr1 + mp);
            const uint32_t h0 = dup_f16(hiblk ? t0.y : t0.x);
            const uint32_t h1 = dup_f16(hiblk ? t1.y : t1.x);

            uint4 bf[4];
            #pragma unroll
            for (int g = 0; g < 4; ++g)
                bf[g] = __ldg(&g_bfrag[(size_t)(mp * 4 + g) * 32 + lane]);

            {   // e = 0 (k 0..15 of pair)
                const uint32_t a0 = hmul2(dec16(q0.x), h0), a2 = hmul2(dec16(q0.y), h0);
                const uint32_t a1 = hmul2(dec16(q1.x), h1), a3 = hmul2(dec16(q1.y), h1);
                #pragma unroll
                for (int g = 0; g < 4; ++g)
                    mma_acc(acc[g][0], acc[g][1], acc[g][2], acc[g][3],
                            a0, a1, a2, a3, bf[g].x, bf[g].y);
            }
            {   // e = 1 (k 16..31 of pair)
                const uint32_t a0 = hmul2(dec16(q0.z), h0), a2 = hmul2(dec16(q0.w), h0);
                const uint32_t a1 = hmul2(dec16(q1.z), h1), a3 = hmul2(dec16(q1.w), h1);
                #pragma unroll
                for (int g = 0; g < 4; ++g)
                    mma_acc(acc[g][0], acc[g][1], acc[g][2], acc[g][3],
                            a0, a1, a2, a3, bf[g].z, bf[g].w);
            }
        }

        // write split-K partials: token cols g*8+2c, 2c+1 ; rows r0, r0+8
        float* base = g_part + (size_t)blockIdx.y * (TOKENS * NFEAT);
        #pragma unroll
        for (int g = 0; g < 4; ++g){
            const int t0c = g * 8 + 2 * c;
            base[(size_t)t0c       * NFEAT + r0    ] = acc[g][0];
            base[(size_t)(t0c + 1) * NFEAT + r0    ] = acc[g][1];
            base[(size_t)t0c       * NFEAT + r0 + 8] = acc[g][2];
            base[(size_t)(t0c + 1) * NFEAT + r0 + 8] = acc[g][3];
        }
    }
    grid_barrier(1);

    // ========== phase 2: split-K reduce + bias (float2 per thread) ==========
    {
        const int i2 = t;                            // 0..131071 covers 32*8192/2
        const float2 b = *reinterpret_cast<const float2*>(bias + ((i2 * 2) & (NFEAT - 1)));
        float2 s = b;
        #pragma unroll
        for (int cp = 0; cp < KSPLIT; ++cp){
            const float2 v = *reinterpret_cast<const float2*>(
                g_part + (size_t)cp * (TOKENS * NFEAT) + (size_t)i2 * 2);
            s.x += v.x; s.y += v.y;
        }
        reinterpret_cast<float2*>(out)[i2] = s;
    }
}

extern "C" void kernel_launch(void* const* d_in, const int* in_sizes, int n_in,
                              void* d_out, int out_size)
{
    const float* inp    = (const float*)d_in[0];
    const int*   qw     = (const int*)  d_in[1];
    const float* scales = (const float*)d_in[2];
    const float* amax   = (const float*)d_in[3];
    const float* bias   = (const float*)d_in[4];
    float* out = (float*)d_out;

    dim3 grid(NFEAT / 64, KSPLIT);
    fp4_fused_kernel<<<grid, 128>>>(qw, scales, inp, amax, bias, out);
}

// round 12
// speedup vs baseline: 1.2825x; 1.0461x over previous
#include <cuda_runtime.h>
#include <cuda_fp16.h>
#include <cstdint>

// FP4(E2M1) weight-only linear, fused persistent kernel:
//   phase 0: fp16 activation fragments (amax folded)
//   phase 1: fp16 mma.sync GEMM, 32 rows/warp, qweight streamed through a
//            PER-WARP 4-stage cp.async SMEM pipeline (no CTA-level syncs)
//   phase 2: split-K reduce + bias
// out[32,8192] = inp[32,8192] @ W^T + bias, W[n,k]=LUT(nib)*scales[n,k/16]*amax

#define TOKENS   32
#define NFEAT    8192
#define KFEAT    8192
#define NWIN     (KFEAT / 16)          // 512 mma k-steps
#define NMP      (NWIN / 2)            // 256 window-pairs
#define KSPLIT   8
#define MP_PER_CTA  (NMP / KSPLIT)     // 32
#define NCTAS    512
#define NST      4                     // cp.async stages (per warp)

__device__ uint4 g_bfrag[NMP * 4 * 32];             // fp16x2 x4 per [mp][g][lane] (2 MB)
__device__ float g_part[KSPLIT * TOKENS * NFEAT];   // split-K partials (8 MB)
__device__ unsigned g_cnt[2];                        // barrier counters (zero-init)
__device__ volatile unsigned g_phase[2];             // barrier phase flags

// ---------- helpers ----------
__device__ __forceinline__ uint32_t smem_u32(const void* p){
    uint32_t a;
    asm("{ .reg .u64 t; cvta.to.shared.u64 t, %1; cvt.u32.u64 %0, t; }" : "=r"(a) : "l"(p));
    return a;
}
#define CPA16(dst, src) asm volatile("cp.async.cg.shared.global [%0], [%1], 16;" :: "r"(dst), "l"(src))
#define CPA_COMMIT()    asm volatile("cp.async.commit_group;")
#define CPA_WAIT3()     asm volatile("cp.async.wait_group 3;")

__device__ __forceinline__ uint32_t dec16(uint32_t b){   // byte -> fp16x2 LUT pair (exact)
    uint32_t h = __byte_perm(0x3E3C3800u, 0x46444240u, b & 0x77u);
    uint32_t r = __byte_perm(h, 0u, 0x1404u);
    return r | ((b & 0x8u) << 12) | ((b & 0x80u) << 24);
}
__device__ __forceinline__ uint32_t hmul2(uint32_t a, uint32_t b){
    uint32_t r; asm("mul.rn.f16x2 %0, %1, %2;" : "=r"(r) : "r"(a), "r"(b)); return r;
}
__device__ __forceinline__ uint32_t dup_f16(float s){
    uint32_t r; asm("cvt.rn.f16x2.f32 %0, %1, %1;" : "=r"(r) : "f"(s)); return r;
}
__device__ __forceinline__ uint32_t pack_f16x2(float lo, float hi){
    uint32_t r; asm("cvt.rn.f16x2.f32 %0, %1, %2;" : "=r"(r) : "f"(hi), "f"(lo)); return r;
}
__device__ __forceinline__ void mma_acc(
    float& d0, float& d1, float& d2, float& d3,
    uint32_t a0, uint32_t a1, uint32_t a2, uint32_t a3,
    uint32_t b0, uint32_t b1)
{
    asm("mma.sync.aligned.m16n8k16.row.col.f32.f16.f16.f32 "
        "{%0,%1,%2,%3}, {%4,%5,%6,%7}, {%8,%9}, {%0,%1,%2,%3};"
        : "+f"(d0), "+f"(d1), "+f"(d2), "+f"(d3)
        : "r"(a0), "r"(a1), "r"(a2), "r"(a3), "r"(b0), "r"(b1));
}

// sense-reversing grid barrier; replay-safe (counter self-resets, phase toggles)
__device__ __forceinline__ void grid_barrier(int b){
    __syncthreads();
    if (threadIdx.x == 0){
        __threadfence();
        unsigned p = g_phase[b];
        unsigned arrived = atomicAdd(&g_cnt[b], 1u) + 1u;
        if (arrived == NCTAS){
            g_cnt[b] = 0u;
            __threadfence();
            g_phase[b] = p + 1u;
        } else {
            while (g_phase[b] == p) { __nanosleep(32); }
        }
    }
    __syncthreads();
    __threadfence();
}

// ---------------- fused persistent kernel ----------------
// grid (64, 8) = 512 CTAs, 128 thr, occ 4 (regs<=128, smem 32KB) -> 1 wave.
__global__ void __launch_bounds__(128, 4) fp4_fused_kernel(
    const int*   __restrict__ qw,       // [N, K/2] one packed byte per int32
    const float* __restrict__ scales,   // [N, K/16]
    const float* __restrict__ inp,      // [M, K]
    const float* __restrict__ amax,     // [1]
    const float* __restrict__ bias,     // [N]
    float*       __restrict__ out)      // [M, N]
{
    // per-warp private staging: [warp][stage][rowgroup j][lane] 16B
    __shared__ __align__(16) char qsm[4 * NST * 4 * 32 * 16];   // 32 KB

    const int tid = threadIdx.x, wid = tid >> 5, lane = tid & 31;
    const int bid = blockIdx.y * 64 + blockIdx.x;
    const int t   = bid * 128 + tid;                  // flat 0..65535

    // ========== phase 0: build fp16 B fragments (one uint2 per thread) ==========
    {
        int e = t >> 1, h = t & 1;
        int bl = e & 31, g = (e >> 5) & 3, mp = e >> 7;
        int bc = bl & 3, n = g * 8 + (bl >> 2);
        int k0 = 32 * mp + 8 * bc + 4 * h;
        const float am = __ldg(amax);
        float4 a = *reinterpret_cast<const float4*>(inp + (size_t)n * KFEAT + k0);
        reinterpret_cast<uint2*>(g_bfrag)[t] =
            make_uint2(pack_f16x2(a.x * am, a.y * am), pack_f16x2(a.z * am, a.w * am));
    }
    grid_barrier(0);

    // ========== phase 1: GEMM, 32 rows/warp, per-warp cp.async q pipeline ====
    {
        const int c  = lane & 3, rl = lane >> 2;
        const int r0 = blockIdx.x * 128 + wid * 32 + rl;   // rows r0,+8,+16,+24
        const int mpb = blockIdx.y * MP_PER_CTA;
        const bool hiblk = (lane & 2) != 0;

        float acc[4][8];
        #pragma unroll
        for (int g = 0; g < 4; ++g)
            #pragma unroll
            for (int j = 0; j < 8; ++j) acc[g][j] = 0.f;

        // cp.async sources: each lane's own uint4 (16B) per rowgroup per mp
        const char* qs0 = (const char*)(reinterpret_cast<const uint4*>(qw + (size_t)(r0     ) * (KFEAT / 2)) + c + (size_t)mpb * 4);
        const char* qs1 = (const char*)(reinterpret_cast<const uint4*>(qw + (size_t)(r0 +  8) * (KFEAT / 2)) + c + (size_t)mpb * 4);
        const char* qs2 = (const char*)(reinterpret_cast<const uint4*>(qw + (size_t)(r0 + 16) * (KFEAT / 2)) + c + (size_t)mpb * 4);
        const char* qs3 = (const char*)(reinterpret_cast<const uint4*>(qw + (size_t)(r0 + 24) * (KFEAT / 2)) + c + (size_t)mpb * 4);

        const float2* sr0 = reinterpret_cast<const float2*>(scales + (size_t)(r0     ) * NWIN);
        const float2* sr1 = reinterpret_cast<const float2*>(scales + (size_t)(r0 +  8) * NWIN);
        const float2* sr2 = reinterpret_cast<const float2*>(scales + (size_t)(r0 + 16) * NWIN);
        const float2* sr3 = reinterpret_cast<const float2*>(scales + (size_t)(r0 + 24) * NWIN);

        // per-warp SMEM base; lane slot within a stage
        const uint32_t warp_base = smem_u32(qsm) + (uint32_t)wid * (NST * 4 * 32 * 16);
        const uint32_t lane_off  = (uint32_t)lane * 16;

        // ---- prologue: issue stages for mp offsets 0..2 ----
        #pragma unroll
        for (int s = 0; s < NST - 1; ++s){
            const uint32_t so = warp_base + (uint32_t)s * (4 * 32 * 16);
            CPA16(so + 0 * 512 + lane_off, qs0 + (size_t)s * 64);
            CPA16(so + 1 * 512 + lane_off, qs1 + (size_t)s * 64);
            CPA16(so + 2 * 512 + lane_off, qs2 + (size_t)s * 64);
            CPA16(so + 3 * 512 + lane_off, qs3 + (size_t)s * 64);
            CPA_COMMIT();
        }

        #pragma unroll 2
        for (int mpl = 0; mpl < MP_PER_CTA; ++mpl){
            const int mp = mpb + mpl;

            // issue stage mpl+3 (empty commit near the tail keeps groups uniform)
            if (mpl + NST - 1 < MP_PER_CTA){
                const uint32_t so = warp_base + (uint32_t)((mpl + NST - 1) & (NST - 1)) * (4 * 32 * 16);
                CPA16(so + 0 * 512 + lane_off, qs0 + (size_t)(mpl + NST - 1) * 64);
                CPA16(so + 1 * 512 + lane_off, qs1 + (size_t)(mpl + NST - 1) * 64);
                CPA16(so + 2 * 512 + lane_off, qs2 + (size_t)(mpl + NST - 1) * 64);
                CPA16(so + 3 * 512 + lane_off, qs3 + (size_t)(mpl + NST - 1) * 64);
            }
            CPA_COMMIT();

            // scales + bfrag via regular loads (L1/L2-friendly)
            const float2 t0 = __ldg(sr0 + mp);
            const float2 t1 = __ldg(sr1 + mp);
            const float2 t2 = __ldg(sr2 + mp);
            const float2 t3 = __ldg(sr3 + mp);
            const uint32_t h0 = dup_f16(hiblk ? t0.y : t0.x);
            const uint32_t h1 = dup_f16(hiblk ? t1.y : t1.x);
            const uint32_t h2 = dup_f16(hiblk ? t2.y : t2.x);
            const uint32_t h3 = dup_f16(hiblk ? t3.y : t3.x);

            uint4 bf[4];
            #pragma unroll
            for (int g = 0; g < 4; ++g)
                bf[g] = __ldg(&g_bfrag[(size_t)(mp * 4 + g) * 32 + lane]);

            // wait until stage mpl's group is complete (<=3 newer pending);
            // each lane reads back exactly the bytes IT copied -> no syncwarp.
            CPA_WAIT3();
            const uint32_t so = warp_base + (uint32_t)(mpl & (NST - 1)) * (4 * 32 * 16);
            uint4 q0, q1, q2, q3;
            asm volatile("ld.shared.v4.u32 {%0,%1,%2,%3}, [%4];" : "=r"(q0.x),"=r"(q0.y),"=r"(q0.z),"=r"(q0.w) : "r"(so + 0 * 512 + lane_off));
            asm volatile("ld.shared.v4.u32 {%0,%1,%2,%3}, [%4];" : "=r"(q1.x),"=r"(q1.y),"=r"(q1.z),"=r"(q1.w) : "r"(so + 1 * 512 + lane_off));
            asm volatile("ld.shared.v4.u32 {%0,%1,%2,%3}, [%4];" : "=r"(q2.x),"=r"(q2.y),"=r"(q2.z),"=r"(q2.w) : "r"(so + 2 * 512 + lane_off));
            asm volatile("ld.shared.v4.u32 {%0,%1,%2,%3}, [%4];" : "=r"(q3.x),"=r"(q3.y),"=r"(q3.z),"=r"(q3.w) : "r"(so + 3 * 512 + lane_off));

            {   // e = 0 (k 0..15 of pair)
                const uint32_t a00 = hmul2(dec16(q0.x), h0), a02 = hmul2(dec16(q0.y), h0);
                const uint32_t a01 = hmul2(dec16(q1.x), h1), a03 = hmul2(dec16(q1.y), h1);
                const uint32_t a10 = hmul2(dec16(q2.x), h2), a12 = hmul2(dec16(q2.y), h2);
                const uint32_t a11 = hmul2(dec16(q3.x), h3), a13 = hmul2(dec16(q3.y), h3);
                #pragma unroll
                for (int g = 0; g < 4; ++g){
                    mma_acc(acc[g][0], acc[g][1], acc[g][2], acc[g][3],
                            a00, a01, a02, a03, bf[g].x, bf[g].y);
                    mma_acc(acc[g][4], acc[g][5], acc[g][6], acc[g][7],
                            a10, a11, a12, a13, bf[g].x, bf[g].y);
                }
            }
            {   // e = 1 (k 16..31 of pair)
                const uint32_t a00 = hmul2(dec16(q0.z), h0), a02 = hmul2(dec16(q0.w), h0);
                const uint32_t a01 = hmul2(dec16(q1.z), h1), a03 = hmul2(dec16(q1.w), h1);
                const uint32_t a10 = hmul2(dec16(q2.z), h2), a12 = hmul2(dec16(q2.w), h2);
                const uint32_t a11 = hmul2(dec16(q3.z), h3), a13 = hmul2(dec16(q3.w), h3);
                #pragma unroll
                for (int g = 0; g < 4; ++g){
                    mma_acc(acc[g][0], acc[g][1], acc[g][2], acc[g][3],
                            a00, a01, a02, a03, bf[g].z, bf[g].w);
                    mma_acc(acc[g][4], acc[g][5], acc[g][6], acc[g][7],
                            a10, a11, a12, a13, bf[g].z, bf[g].w);
                }
            }
        }

        // write split-K partials: token cols g*8+2c, 2c+1 ; rows r0, +8, +16, +24
        float* base = g_part + (size_t)blockIdx.y * (TOKENS * NFEAT);
        #pragma unroll
        for (int g = 0; g < 4; ++g){
            const int t0c = g * 8 + 2 * c;
            base[(size_t)t0c       * NFEAT + r0     ] = acc[g][0];
            base[(size_t)(t0c + 1) * NFEAT + r0     ] = acc[g][1];
            base[(size_t)t0c       * NFEAT + r0 +  8] = acc[g][2];
            base[(size_t)(t0c + 1) * NFEAT + r0 +  8] = acc[g][3];
            base[(size_t)t0c       * NFEAT + r0 + 16] = acc[g][4];
            base[(size_t)(t0c + 1) * NFEAT + r0 + 16] = acc[g][5];
            base[(size_t)t0c       * NFEAT + r0 + 24] = acc[g][6];
            base[(size_t)(t0c + 1) * NFEAT + r0 + 24] = acc[g][7];
        }
    }
    grid_barrier(1);

    // ========== phase 2: split-K reduce + bias (one float4 per thread) ==========
    {
        const int i4 = t;
        const float4 b = *reinterpret_cast<const float4*>(bias + ((i4 * 4) & (NFEAT - 1)));
        float4 s = b;
        #pragma unroll
        for (int cp = 0; cp < KSPLIT; ++cp){
            const float4 v = *reinterpret_cast<const float4*>(
                g_part + (size_t)cp * (TOKENS * NFEAT) + (size_t)i4 * 4);
            s.x += v.x; s.y += v.y; s.z += v.z; s.w += v.w;
        }
        reinterpret_cast<float4*>(out)[i4] = s;
    }
}

extern "C" void kernel_launch(void* const* d_in, const int* in_sizes, int n_in,
                              void* d_out, int out_size)
{
    const float* inp    = (const float*)d_in[0];
    const int*   qw     = (const int*)  d_in[1];
    const float* scales = (const float*)d_in[2];
    const float* amax   = (const float*)d_in[3];
    const float* bias   = (const float*)d_in[4];
    float* out = (float*)d_out;

    dim3 grid(NFEAT / 128, KSPLIT);
    fp4_fused_kernel<<<grid, 128>>>(qw, scales, inp, amax, bias, out);
}